// round 2
// baseline (speedup 1.0000x reference)
#include <cuda_runtime.h>
#include <math.h>

// ---------------------------------------------------------------------------
// EdgeMaskGenerator: out[e] = sigmoid( relu(x_e @ W1 + b1) @ W2 + b2 )
// x_e = [h[src], rel_table[type], rel_table[q], time_table[time]]  (4*128)
//
// Decomposition: x@W1 = h[src]@W1a + rel_table[type]@W1b + rel_table[q]@W1c
//                       + time_table[time]@W1d
// Precompute per-node / per-rel / per-time projections once, then the edge
// pass is 3 gathers + relu-add + 128-dot + sigmoid.
//
// NOTE: JAX default config downgrades int64 -> int32, so all index inputs
// are int32 on the wire.
// ---------------------------------------------------------------------------

#define D 128
#define MAX_NODES 100000
#define MAX_RELS  500
#define MAX_TIMES 1000

__device__ __align__(128) float g_node_proj[(size_t)MAX_NODES * D];
__device__ __align__(128) float g_rel_proj[(size_t)MAX_RELS * D];
__device__ __align__(128) float g_time_proj[(size_t)MAX_TIMES * D];
__device__ __align__(128) float g_const_vec[D];

// ---------------------------------------------------------------------------
// SGEMM: C[M,128] = A[M,128] @ W1[w_off : w_off+128, 0:128]
// BLOCK_M = 64, 256 threads, each thread computes an 8x4 register tile.
// ---------------------------------------------------------------------------
#define BM 64
#define KC 32

__global__ __launch_bounds__(256) void proj_gemm_kernel(
    const float* __restrict__ A, const float* __restrict__ W1,
    int w_off, int dst_sel, int M)
{
    __shared__ float As[KC][BM];        // 8 KB, transposed A tile
    __shared__ float Bs[KC][D];         // 16 KB

    float* __restrict__ C = (dst_sel == 0) ? g_node_proj
                          : (dst_sel == 1) ? g_rel_proj
                                           : g_time_proj;

    const int tid = threadIdx.x;
    const int tx  = tid & 31;           // N group: 4 cols each
    const int ty  = tid >> 5;           // M group: 8 rows each
    const int m0  = blockIdx.x * BM;

    float acc[8][4];
#pragma unroll
    for (int i = 0; i < 8; i++)
#pragma unroll
        for (int j = 0; j < 4; j++) acc[i][j] = 0.f;

    for (int k0 = 0; k0 < D; k0 += KC) {
        // Load A tile (64 x 32) as float4, store transposed.
#pragma unroll
        for (int i = tid; i < BM * KC / 4; i += 256) {
            int row = i >> 3;           // /(KC/4)
            int c4  = i & 7;
            float4 v = make_float4(0.f, 0.f, 0.f, 0.f);
            int grow = m0 + row;
            if (grow < M)
                v = *(const float4*)(A + (size_t)grow * D + k0 + c4 * 4);
            As[c4 * 4 + 0][row] = v.x;
            As[c4 * 4 + 1][row] = v.y;
            As[c4 * 4 + 2][row] = v.z;
            As[c4 * 4 + 3][row] = v.w;
        }
        // Load B tile (32 x 128) as float4, contiguous.
#pragma unroll
        for (int i = tid; i < KC * D / 4; i += 256) {
            int kk = i >> 5;            // /(D/4)
            int c4 = i & 31;
            *(float4*)(&Bs[kk][c4 * 4]) =
                *(const float4*)(W1 + (size_t)(w_off + k0 + kk) * D + c4 * 4);
        }
        __syncthreads();

#pragma unroll 8
        for (int kk = 0; kk < KC; kk++) {
            float a[8];
#pragma unroll
            for (int i = 0; i < 8; i++) a[i] = As[kk][ty * 8 + i];
            float4 b = *(const float4*)(&Bs[kk][tx * 4]);
#pragma unroll
            for (int i = 0; i < 8; i++) {
                acc[i][0] += a[i] * b.x;
                acc[i][1] += a[i] * b.y;
                acc[i][2] += a[i] * b.z;
                acc[i][3] += a[i] * b.w;
            }
        }
        __syncthreads();
    }

#pragma unroll
    for (int i = 0; i < 8; i++) {
        int grow = m0 + ty * 8 + i;
        if (grow < M) {
            float4 v = make_float4(acc[i][0], acc[i][1], acc[i][2], acc[i][3]);
            *(float4*)(C + (size_t)grow * D + tx * 4) = v;
        }
    }
}

// ---------------------------------------------------------------------------
// const_vec[j] = b1[j] + sum_k rel_table[q*128+k] * W1[(256+k)*128 + j]
// ---------------------------------------------------------------------------
__global__ void const_vec_kernel(const float* __restrict__ rel_table,
                                 const float* __restrict__ W1,
                                 const float* __restrict__ b1,
                                 const int* __restrict__ qptr)
{
    int j = threadIdx.x;
    int q = qptr[0];
    float s = b1[j];
    const float* rq = rel_table + (size_t)q * D;
#pragma unroll 8
    for (int k = 0; k < D; k++)
        s += rq[k] * W1[(size_t)(256 + k) * D + j];
    g_const_vec[j] = s;
}

// ---------------------------------------------------------------------------
// Edge pass: one warp per edge. Lane l handles floats [4l, 4l+4).
// Indices are int32 (JAX x64 disabled).
// ---------------------------------------------------------------------------
__global__ __launch_bounds__(256) void edge_kernel(
    const int* __restrict__ edge_src,   // edge_index row 0
    const int* __restrict__ edge_type,
    const int* __restrict__ edge_time,
    const float* __restrict__ W2,
    const float* __restrict__ b2,
    float* __restrict__ out, int E)
{
    int gw   = (int)((blockIdx.x * (unsigned)blockDim.x + threadIdx.x) >> 5);
    int lane = threadIdx.x & 31;
    if (gw >= E) return;

    int s = __ldg(edge_src + gw);
    int r = __ldg(edge_type + gw);
    int t = __ldg(edge_time + gw);

    float4 a  = ((const float4*)g_node_proj)[(size_t)s * 32 + lane];
    float4 b  = ((const float4*)g_rel_proj )[(size_t)r * 32 + lane];
    float4 c  = ((const float4*)g_time_proj)[(size_t)t * 32 + lane];
    float4 cv = ((const float4*)g_const_vec)[lane];
    float4 w  = __ldg((const float4*)W2 + lane);

    float x0 = fmaxf(a.x + b.x + c.x + cv.x, 0.f);
    float x1 = fmaxf(a.y + b.y + c.y + cv.y, 0.f);
    float x2 = fmaxf(a.z + b.z + c.z + cv.z, 0.f);
    float x3 = fmaxf(a.w + b.w + c.w + cv.w, 0.f);

    float dot = x0 * w.x + x1 * w.y + x2 * w.z + x3 * w.w;
#pragma unroll
    for (int off = 16; off; off >>= 1)
        dot += __shfl_xor_sync(0xffffffffu, dot, off);

    if (lane == 0) {
        float alpha = dot + __ldg(b2);
        out[gw] = 1.f / (1.f + expf(-alpha));
    }
}

// ---------------------------------------------------------------------------
// Launch
// ---------------------------------------------------------------------------
extern "C" void kernel_launch(void* const* d_in, const int* in_sizes, int n_in,
                              void* d_out, int out_size)
{
    const float* h          = (const float*)d_in[0];
    const int*   edge_index = (const int*)d_in[1];
    const int*   edge_type  = (const int*)d_in[2];
    const int*   edge_time  = (const int*)d_in[3];
    const int*   query_rel  = (const int*)d_in[4];
    const float* rel_table  = (const float*)d_in[5];
    const float* time_table = (const float*)d_in[6];
    const float* W1         = (const float*)d_in[7];
    const float* b1         = (const float*)d_in[8];
    const float* W2         = (const float*)d_in[9];
    const float* b2         = (const float*)d_in[10];
    float*       out        = (float*)d_out;

    const int n_nodes = in_sizes[0] / D;
    const int n_rels  = in_sizes[5] / D;
    const int n_times = in_sizes[6] / D;
    const int E       = in_sizes[2];

    // Precompute projections (W1 row blocks: [0:128)=src, [128:256)=rel,
    // [256:384)=query, [384:512)=time).
    proj_gemm_kernel<<<(n_nodes + BM - 1) / BM, 256>>>(h,          W1,   0, 0, n_nodes);
    proj_gemm_kernel<<<(n_rels  + BM - 1) / BM, 256>>>(rel_table,  W1, 128, 1, n_rels);
    proj_gemm_kernel<<<(n_times + BM - 1) / BM, 256>>>(time_table, W1, 384, 2, n_times);
    const_vec_kernel<<<1, D>>>(rel_table, W1, b1, query_rel);

    // Edge pass: one warp per edge, 8 warps per block.
    int blocks = (E + 7) / 8;
    edge_kernel<<<blocks, 256>>>(edge_index, edge_type, edge_time, W2, b2, out, E);
}

// round 3
// speedup vs baseline: 1.1985x; 1.1985x over previous
#include <cuda_runtime.h>
#include <cuda_fp16.h>
#include <math.h>

// ---------------------------------------------------------------------------
// EdgeMaskGenerator: out[e] = sigmoid( relu(x_e @ W1 + b1) @ W2 + b2 )
// x_e = [h[src], rel_table[type], rel_table[q], time_table[time]]  (4*128)
//
// Decomposition: x@W1 = h[src]@W1a + rel_table[type]@W1b + rel_table[q]@W1c
//                       + time_table[time]@W1d
// Projections precomputed once (stored fp16 to halve edge-pass L2 traffic),
// edge pass = 3 gathers + relu-add + 128-dot + sigmoid.
// ---------------------------------------------------------------------------

#define D 128
#define MAX_NODES 100000
#define MAX_RELS  500
#define MAX_TIMES 1000

__device__ __align__(128) __half g_node_proj[(size_t)MAX_NODES * D];
__device__ __align__(128) __half g_rel_proj[(size_t)MAX_RELS * D];
__device__ __align__(128) __half g_time_proj[(size_t)MAX_TIMES * D];
__device__ __align__(128) float  g_const_vec[D];

// ---- packed f32x2 helpers (sm_103a FFMA2) ---------------------------------
__device__ __forceinline__ unsigned long long pack2(float x, float y) {
    unsigned long long r;
    asm("mov.b64 %0, {%1, %2};"
        : "=l"(r) : "r"(__float_as_uint(x)), "r"(__float_as_uint(y)));
    return r;
}
__device__ __forceinline__ void unpack2(unsigned long long v, float& x, float& y) {
    unsigned a, b;
    asm("mov.b64 {%0, %1}, %2;" : "=r"(a), "=r"(b) : "l"(v));
    x = __uint_as_float(a); y = __uint_as_float(b);
}
__device__ __forceinline__ unsigned long long fma2(
    unsigned long long a, unsigned long long b, unsigned long long c) {
    unsigned long long d;
    asm("fma.rn.f32x2 %0, %1, %2, %3;" : "=l"(d) : "l"(a), "l"(b), "l"(c));
    return d;
}

// ---------------------------------------------------------------------------
// GEMM tile body: C[m0:m0+64, 0:128] (fp16) = A[m0:.., 0:128] @ W1[w_off+k][j]
// 256 threads, 8x4 register tile per thread, packed f32x2 FMA.
// ---------------------------------------------------------------------------
#define BM 64
#define KC 32

__device__ __forceinline__ void gemm_tile(
    const float* __restrict__ A, const float* __restrict__ W1,
    int w_off, __half* __restrict__ C, int M, int m0)
{
    __shared__ float As[KC][BM];
    __shared__ float Bs[KC][D];

    const int tid = threadIdx.x;
    const int tx  = tid & 31;           // 4 cols each
    const int ty  = tid >> 5;           // 8 rows each

    unsigned long long acc2[8][2];
#pragma unroll
    for (int i = 0; i < 8; i++) { acc2[i][0] = 0ull; acc2[i][1] = 0ull; }

    for (int k0 = 0; k0 < D; k0 += KC) {
#pragma unroll
        for (int i = tid; i < BM * KC / 4; i += 256) {
            int row = i >> 3;
            int c4  = i & 7;
            float4 v = make_float4(0.f, 0.f, 0.f, 0.f);
            int grow = m0 + row;
            if (grow < M)
                v = *(const float4*)(A + (size_t)grow * D + k0 + c4 * 4);
            As[c4 * 4 + 0][row] = v.x;
            As[c4 * 4 + 1][row] = v.y;
            As[c4 * 4 + 2][row] = v.z;
            As[c4 * 4 + 3][row] = v.w;
        }
#pragma unroll
        for (int i = tid; i < KC * D / 4; i += 256) {
            int kk = i >> 5;
            int c4 = i & 31;
            *(float4*)(&Bs[kk][c4 * 4]) =
                *(const float4*)(W1 + (size_t)(w_off + k0 + kk) * D + c4 * 4);
        }
        __syncthreads();

#pragma unroll 8
        for (int kk = 0; kk < KC; kk++) {
            float4 b = *(const float4*)(&Bs[kk][tx * 4]);
            unsigned long long b01 = pack2(b.x, b.y);
            unsigned long long b23 = pack2(b.z, b.w);
#pragma unroll
            for (int i = 0; i < 8; i++) {
                float av = As[kk][ty * 8 + i];
                unsigned long long aa = pack2(av, av);
                acc2[i][0] = fma2(aa, b01, acc2[i][0]);
                acc2[i][1] = fma2(aa, b23, acc2[i][1]);
            }
        }
        __syncthreads();
    }

#pragma unroll
    for (int i = 0; i < 8; i++) {
        int grow = m0 + ty * 8 + i;
        if (grow < M) {
            float x0, x1, x2, x3;
            unpack2(acc2[i][0], x0, x1);
            unpack2(acc2[i][1], x2, x3);
            __half2 h01 = __floats2half2_rn(x0, x1);
            __half2 h23 = __floats2half2_rn(x2, x3);
            uint2 v;
            v.x = *(unsigned*)&h01;
            v.y = *(unsigned*)&h23;
            *(uint2*)(C + (size_t)grow * D + tx * 4) = v;
        }
    }
}

// Node projection (big GEMM).
__global__ __launch_bounds__(256) void node_gemm_kernel(
    const float* __restrict__ h, const float* __restrict__ W1, int M)
{
    gemm_tile(h, W1, 0, g_node_proj, M, blockIdx.x * BM);
}

// rel-proj + time-proj + const_vec, one grid.
__global__ __launch_bounds__(256) void small_tables_kernel(
    const float* __restrict__ rel_table, const float* __restrict__ time_table,
    const float* __restrict__ W1, const float* __restrict__ b1,
    const int* __restrict__ qptr, int n_rels, int n_times)
{
    const int nb_rel  = (n_rels  + BM - 1) / BM;
    const int nb_time = (n_times + BM - 1) / BM;
    int bx = blockIdx.x;

    if (bx < nb_rel) {
        gemm_tile(rel_table, W1, 128, g_rel_proj, n_rels, bx * BM);
        return;
    }
    bx -= nb_rel;
    if (bx < nb_time) {
        gemm_tile(time_table, W1, 384, g_time_proj, n_times, bx * BM);
        return;
    }

    // const_vec block: 256 threads, K split 2-way, unroll 16.
    __shared__ float rq_s[D];
    __shared__ float red[D];
    const int tid = threadIdx.x;
    const int q = qptr[0];
    if (tid < D) rq_s[tid] = __ldg(rel_table + (size_t)q * D + tid);
    __syncthreads();

    const int j  = tid & 127;
    const int kh = tid >> 7;            // 0 or 1
    float s0 = 0.f, s1 = 0.f;
    const float* Wc = W1 + (size_t)(256 + kh * 64) * D + j;
#pragma unroll 16
    for (int k = 0; k < 64; k += 2) {
        s0 += rq_s[kh * 64 + k]     * __ldg(Wc + (size_t)k * D);
        s1 += rq_s[kh * 64 + k + 1] * __ldg(Wc + (size_t)(k + 1) * D);
    }
    float s = s0 + s1;
    if (kh == 1) red[j] = s;
    __syncthreads();
    if (kh == 0) g_const_vec[j] = s + red[j] + __ldg(b1 + j);
}

// ---------------------------------------------------------------------------
// Edge pass: one warp per edge, lane l handles features [4l, 4l+4).
// ---------------------------------------------------------------------------
__global__ __launch_bounds__(256) void edge_kernel(
    const int* __restrict__ edge_src,
    const int* __restrict__ edge_type,
    const int* __restrict__ edge_time,
    const float* __restrict__ W2,
    const float* __restrict__ b2,
    float* __restrict__ out, int E)
{
    int gw   = (int)((blockIdx.x * (unsigned)blockDim.x + threadIdx.x) >> 5);
    int lane = threadIdx.x & 31;
    if (gw >= E) return;

    int s = __ldg(edge_src + gw);
    int r = __ldg(edge_type + gw);
    int t = __ldg(edge_time + gw);

    // 128 halfs per row = 32 uint2; lane reads 4 halfs (features 4l..4l+3).
    uint2 av = ((const uint2*)g_node_proj)[(size_t)s * 32 + lane];
    uint2 bv = ((const uint2*)g_rel_proj )[(size_t)r * 32 + lane];
    uint2 cv2= ((const uint2*)g_time_proj)[(size_t)t * 32 + lane];
    float4 cc = ((const float4*)g_const_vec)[lane];
    float4 w  = __ldg((const float4*)W2 + lane);

    float2 a01 = __half22float2(*(__half2*)&av.x);
    float2 a23 = __half22float2(*(__half2*)&av.y);
    float2 b01 = __half22float2(*(__half2*)&bv.x);
    float2 b23 = __half22float2(*(__half2*)&bv.y);
    float2 c01 = __half22float2(*(__half2*)&cv2.x);
    float2 c23 = __half22float2(*(__half2*)&cv2.y);

    float x0 = fmaxf(a01.x + b01.x + c01.x + cc.x, 0.f);
    float x1 = fmaxf(a01.y + b01.y + c01.y + cc.y, 0.f);
    float x2 = fmaxf(a23.x + b23.x + c23.x + cc.z, 0.f);
    float x3 = fmaxf(a23.y + b23.y + c23.y + cc.w, 0.f);

    float dot = x0 * w.x + x1 * w.y + x2 * w.z + x3 * w.w;
#pragma unroll
    for (int off = 16; off; off >>= 1)
        dot += __shfl_xor_sync(0xffffffffu, dot, off);

    if (lane == 0) {
        float alpha = dot + __ldg(b2);
        out[gw] = 1.f / (1.f + expf(-alpha));
    }
}

// ---------------------------------------------------------------------------
extern "C" void kernel_launch(void* const* d_in, const int* in_sizes, int n_in,
                              void* d_out, int out_size)
{
    const float* h          = (const float*)d_in[0];
    const int*   edge_index = (const int*)d_in[1];
    const int*   edge_type  = (const int*)d_in[2];
    const int*   edge_time  = (const int*)d_in[3];
    const int*   query_rel  = (const int*)d_in[4];
    const float* rel_table  = (const float*)d_in[5];
    const float* time_table = (const float*)d_in[6];
    const float* W1         = (const float*)d_in[7];
    const float* b1         = (const float*)d_in[8];
    const float* W2         = (const float*)d_in[9];
    const float* b2         = (const float*)d_in[10];
    float*       out        = (float*)d_out;

    const int n_nodes = in_sizes[0] / D;
    const int n_rels  = in_sizes[5] / D;
    const int n_times = in_sizes[6] / D;
    const int E       = in_sizes[2];

    const int nb_rel  = (n_rels  + BM - 1) / BM;
    const int nb_time = (n_times + BM - 1) / BM;

    small_tables_kernel<<<nb_rel + nb_time + 1, 256>>>(
        rel_table, time_table, W1, b1, query_rel, n_rels, n_times);
    node_gemm_kernel<<<(n_nodes + BM - 1) / BM, 256>>>(h, W1, n_nodes);

    int blocks = (E + 7) / 8;
    edge_kernel<<<blocks, 256>>>(edge_index, edge_type, edge_time, W2, b2, out, E);
}

// round 4
// speedup vs baseline: 1.6486x; 1.3756x over previous
#include <cuda_runtime.h>
#include <cuda_fp16.h>
#include <math.h>

// ---------------------------------------------------------------------------
// out[e] = sigmoid( relu(x_e @ W1 + b1) @ W2 + b2 ),
// x_e = [h[src], rel_table[type], rel_table[q], time_table[time]]
//
// Decomposed: per-node / per-rel / per-time 128x128 projections precomputed
// once (fp16). Query projection + b1 folded into the rel table rows.
// Edge pass = 3 uint4-gathers + relu-add + 128-dot + sigmoid.
// ---------------------------------------------------------------------------

#define D 128
#define MAX_NODES 100000
#define MAX_RELS  500
#define MAX_TIMES 1000

__device__ __align__(128) __half g_node_proj[(size_t)MAX_NODES * D];
__device__ __align__(128) __half g_rel_proj[(size_t)MAX_RELS * D];   // + rq@W1c + b1
__device__ __align__(128) __half g_time_proj[(size_t)MAX_TIMES * D];

// ---- packed f32x2 helpers (sm_103a FFMA2) ---------------------------------
__device__ __forceinline__ unsigned long long pack2(float x, float y) {
    unsigned long long r;
    asm("mov.b64 %0, {%1, %2};"
        : "=l"(r) : "r"(__float_as_uint(x)), "r"(__float_as_uint(y)));
    return r;
}
__device__ __forceinline__ void unpack2(unsigned long long v, float& x, float& y) {
    unsigned a, b;
    asm("mov.b64 {%0, %1}, %2;" : "=r"(a), "=r"(b) : "l"(v));
    x = __uint_as_float(a); y = __uint_as_float(b);
}
__device__ __forceinline__ unsigned long long fma2(
    unsigned long long a, unsigned long long b, unsigned long long c) {
    unsigned long long d;
    asm("fma.rn.f32x2 %0, %1, %2, %3;" : "=l"(d) : "l"(a), "l"(b), "l"(c));
    return d;
}

#define BM 64
#define KC 32

// ---------------------------------------------------------------------------
// Fused prep kernel. One grid covers:
//   [0, nb_node)                 : g_node_proj = h @ W1[0:128]
//   [nb_node, nb_node+nb_rel)    : g_rel_proj  = rel_table @ W1[128:256]
//                                              + rq @ W1[256:384] + b1
//   [.., +nb_time)               : g_time_proj = time_table @ W1[384:512]
// 256 threads, 8x4 register tile per thread, packed f32x2 FMA.
// ---------------------------------------------------------------------------
__global__ __launch_bounds__(256) void prep_kernel(
    const float* __restrict__ h,
    const float* __restrict__ rel_table,
    const float* __restrict__ time_table,
    const float* __restrict__ W1,
    const float* __restrict__ b1,
    const int* __restrict__ qptr,
    int n_nodes, int n_rels, int n_times)
{
    __shared__ float As[KC][BM];
    __shared__ float Bs[KC][D];
    __shared__ float rq_s[D];

    const int nb_node = (n_nodes + BM - 1) / BM;
    const int nb_rel  = (n_rels  + BM - 1) / BM;

    const float* A;
    __half* C;
    int w_off, M, m0;
    bool is_rel = false;

    int bx = blockIdx.x;
    if (bx < nb_node) {
        A = h; C = g_node_proj; w_off = 0; M = n_nodes; m0 = bx * BM;
    } else if (bx < nb_node + nb_rel) {
        A = rel_table; C = g_rel_proj; w_off = 128; M = n_rels;
        m0 = (bx - nb_node) * BM; is_rel = true;
    } else {
        A = time_table; C = g_time_proj; w_off = 384; M = n_times;
        m0 = (bx - nb_node - nb_rel) * BM;
    }

    const int tid = threadIdx.x;
    const int tx  = tid & 31;           // 4 cols each
    const int ty  = tid >> 5;           // 8 rows each

    if (is_rel && tid < D) {
        int q = qptr[0];
        rq_s[tid] = __ldg(rel_table + (size_t)q * D + tid);
    }

    unsigned long long acc2[8][2];
#pragma unroll
    for (int i = 0; i < 8; i++) { acc2[i][0] = 0ull; acc2[i][1] = 0ull; }

    for (int k0 = 0; k0 < D; k0 += KC) {
        __syncthreads();
#pragma unroll
        for (int i = tid; i < BM * KC / 4; i += 256) {
            int row = i >> 3;
            int c4  = i & 7;
            float4 v = make_float4(0.f, 0.f, 0.f, 0.f);
            int grow = m0 + row;
            if (grow < M)
                v = *(const float4*)(A + (size_t)grow * D + k0 + c4 * 4);
            As[c4 * 4 + 0][row] = v.x;
            As[c4 * 4 + 1][row] = v.y;
            As[c4 * 4 + 2][row] = v.z;
            As[c4 * 4 + 3][row] = v.w;
        }
#pragma unroll
        for (int i = tid; i < KC * D / 4; i += 256) {
            int kk = i >> 5;
            int c4 = i & 31;
            *(float4*)(&Bs[kk][c4 * 4]) =
                *(const float4*)(W1 + (size_t)(w_off + k0 + kk) * D + c4 * 4);
        }
        __syncthreads();

#pragma unroll 8
        for (int kk = 0; kk < KC; kk++) {
            float4 b = *(const float4*)(&Bs[kk][tx * 4]);
            unsigned long long b01 = pack2(b.x, b.y);
            unsigned long long b23 = pack2(b.z, b.w);
#pragma unroll
            for (int i = 0; i < 8; i++) {
                float av = As[kk][ty * 8 + i];
                unsigned long long aa = pack2(av, av);
                acc2[i][0] = fma2(aa, b01, acc2[i][0]);
                acc2[i][1] = fma2(aa, b23, acc2[i][1]);
            }
        }
    }

    // Column-constant bias: rel blocks fold in rq @ W1[256:384] + b1.
    float4 cbias = make_float4(0.f, 0.f, 0.f, 0.f);
    if (is_rel) {
        const float* Wc = W1 + (size_t)256 * D + tx * 4;
#pragma unroll 8
        for (int k = 0; k < D; k++) {
            float4 wv = __ldg((const float4*)(Wc + (size_t)k * D));
            float rv  = rq_s[k];
            cbias.x += rv * wv.x;
            cbias.y += rv * wv.y;
            cbias.z += rv * wv.z;
            cbias.w += rv * wv.w;
        }
        float4 bb = __ldg((const float4*)b1 + tx);
        cbias.x += bb.x; cbias.y += bb.y; cbias.z += bb.z; cbias.w += bb.w;
    }

#pragma unroll
    for (int i = 0; i < 8; i++) {
        int grow = m0 + ty * 8 + i;
        if (grow < M) {
            float x0, x1, x2, x3;
            unpack2(acc2[i][0], x0, x1);
            unpack2(acc2[i][1], x2, x3);
            __half2 h01 = __floats2half2_rn(x0 + cbias.x, x1 + cbias.y);
            __half2 h23 = __floats2half2_rn(x2 + cbias.z, x3 + cbias.w);
            uint2 v;
            v.x = *(unsigned*)&h01;
            v.y = *(unsigned*)&h23;
            *(uint2*)(C + (size_t)grow * D + tx * 4) = v;
        }
    }
}

// ---------------------------------------------------------------------------
// Edge pass: 16 lanes per edge, lane l handles features [8l, 8l+8) via one
// uint4 (16B) load per table. 2 edges per warp.
// ---------------------------------------------------------------------------
__global__ __launch_bounds__(256) void edge_kernel(
    const int* __restrict__ edge_src,
    const int* __restrict__ edge_type,
    const int* __restrict__ edge_time,
    const float* __restrict__ W2,
    const float* __restrict__ b2,
    float* __restrict__ out, int E)
{
    unsigned gt = blockIdx.x * 256u + threadIdx.x;
    int e = (int)(gt >> 4);
    int l = threadIdx.x & 15;
    if (e >= E) return;

    int s = __ldg(edge_src + e);
    int r = __ldg(edge_type + e);
    int t = __ldg(edge_time + e);

    // 128 halfs per row = 16 uint4 of 8 halfs each.
    uint4 av = ((const uint4*)g_node_proj)[(size_t)s * 16 + l];
    uint4 bv = ((const uint4*)g_rel_proj )[(size_t)r * 16 + l];
    uint4 cv = ((const uint4*)g_time_proj)[(size_t)t * 16 + l];

    float4 w0 = __ldg((const float4*)W2 + l * 2);
    float4 w1 = __ldg((const float4*)W2 + l * 2 + 1);

    float dot;
    {
        float2 a0 = __half22float2(*(__half2*)&av.x);
        float2 b0 = __half22float2(*(__half2*)&bv.x);
        float2 c0 = __half22float2(*(__half2*)&cv.x);
        float2 a1 = __half22float2(*(__half2*)&av.y);
        float2 b1v= __half22float2(*(__half2*)&bv.y);
        float2 c1 = __half22float2(*(__half2*)&cv.y);
        float x0 = fmaxf(a0.x + b0.x + c0.x, 0.f);
        float x1 = fmaxf(a0.y + b0.y + c0.y, 0.f);
        float x2 = fmaxf(a1.x + b1v.x + c1.x, 0.f);
        float x3 = fmaxf(a1.y + b1v.y + c1.y, 0.f);
        dot = x0 * w0.x + x1 * w0.y + x2 * w0.z + x3 * w0.w;
    }
    {
        float2 a0 = __half22float2(*(__half2*)&av.z);
        float2 b0 = __half22float2(*(__half2*)&bv.z);
        float2 c0 = __half22float2(*(__half2*)&cv.z);
        float2 a1 = __half22float2(*(__half2*)&av.w);
        float2 b1v= __half22float2(*(__half2*)&bv.w);
        float2 c1 = __half22float2(*(__half2*)&cv.w);
        float x4 = fmaxf(a0.x + b0.x + c0.x, 0.f);
        float x5 = fmaxf(a0.y + b0.y + c0.y, 0.f);
        float x6 = fmaxf(a1.x + b1v.x + c1.x, 0.f);
        float x7 = fmaxf(a1.y + b1v.y + c1.y, 0.f);
        dot += x4 * w1.x + x5 * w1.y + x6 * w1.z + x7 * w1.w;
    }

#pragma unroll
    for (int off = 8; off; off >>= 1)
        dot += __shfl_xor_sync(0xffffffffu, dot, off);

    if (l == 0) {
        float alpha = dot + __ldg(b2);
        out[e] = 1.f / (1.f + expf(-alpha));
    }
}

// ---------------------------------------------------------------------------
extern "C" void kernel_launch(void* const* d_in, const int* in_sizes, int n_in,
                              void* d_out, int out_size)
{
    const float* h          = (const float*)d_in[0];
    const int*   edge_index = (const int*)d_in[1];
    const int*   edge_type  = (const int*)d_in[2];
    const int*   edge_time  = (const int*)d_in[3];
    const int*   query_rel  = (const int*)d_in[4];
    const float* rel_table  = (const float*)d_in[5];
    const float* time_table = (const float*)d_in[6];
    const float* W1         = (const float*)d_in[7];
    const float* b1         = (const float*)d_in[8];
    const float* W2         = (const float*)d_in[9];
    const float* b2         = (const float*)d_in[10];
    float*       out        = (float*)d_out;

    const int n_nodes = in_sizes[0] / D;
    const int n_rels  = in_sizes[5] / D;
    const int n_times = in_sizes[6] / D;
    const int E       = in_sizes[2];

    const int nb_node = (n_nodes + BM - 1) / BM;
    const int nb_rel  = (n_rels  + BM - 1) / BM;
    const int nb_time = (n_times + BM - 1) / BM;

    prep_kernel<<<nb_node + nb_rel + nb_time, 256>>>(
        h, rel_table, time_table, W1, b1, query_rel,
        n_nodes, n_rels, n_times);

    // 16 lanes per edge -> 16 edges per 256-thread block.
    edge_kernel<<<(E + 15) / 16, 256>>>(
        edge_index, edge_type, edge_time, W2, b2, out, E);
}